// round 5
// baseline (speedup 1.0000x reference)
#include <cuda_runtime.h>

// ---------------- problem constants ----------------
#define Bq      4
#define Sq      2048
#define Tq      (Bq * Sq)      // 8192 tokens
#define Dd      384
#define QKd     48
#define Ed      768
#define Hd      1632           // 2*QK + 2*E
#define NBq     8
#define VOCABq  100

// ---------------- scratch (static device globals; no cudaMalloc allowed) ----
__device__ float g_x[Tq * Dd];                       // residual stream (12.6 MB)
__device__ float g_xn[Tq * Dd];                      // LN output       (12.6 MB)
__device__ float g_h[(size_t)Tq * Hd];               // block GEMM out  (53.5 MB)
__device__ float g_cat[(size_t)Tq * Ed];             // [loc | attn]    (25.2 MB)
__device__ float g_vt[(size_t)Bq * Dd * Sq];         // V transposed    (12.6 MB)
__device__ float g_p[(size_t)Bq * Sq * Sq];          // attention probs (67 MB)

// ---------------- small helpers ----------------
__device__ __forceinline__ float warp_sum(float v) {
#pragma unroll
    for (int o = 16; o; o >>= 1) v += __shfl_xor_sync(0xffffffffu, v, o);
    return v;
}
__device__ __forceinline__ float warp_max(float v) {
#pragma unroll
    for (int o = 16; o; o >>= 1) v = fmaxf(v, __shfl_xor_sync(0xffffffffu, v, o));
    return v;
}

// ---------------- embed (sin/cos) + LayerNorm, one block per token ---------
__global__ void embed_ln_kernel(const int* __restrict__ q,
                                const float* __restrict__ freqs,
                                const float* __restrict__ g,
                                const float* __restrict__ b,
                                float* __restrict__ y) {
    int t = blockIdx.x;
    int tid = threadIdx.x;   // 128 threads, 3 dims each
    float qv = (float)q[t];
    float v[3];
#pragma unroll
    for (int k = 0; k < 3; k++) {
        int d = tid + k * 128;
        float ang;
        if (d < Dd / 2) { ang = qv * freqs[d];          v[k] = sinf(ang); }
        else            { ang = qv * freqs[d - Dd / 2]; v[k] = cosf(ang); }
    }
    float s = v[0] + v[1] + v[2];
    float sq = v[0]*v[0] + v[1]*v[1] + v[2]*v[2];
    s = warp_sum(s); sq = warp_sum(sq);
    __shared__ float shs[4], shq[4], mr[2];
    if ((tid & 31) == 0) { shs[tid >> 5] = s; shq[tid >> 5] = sq; }
    __syncthreads();
    if (tid == 0) {
        float ts = shs[0] + shs[1] + shs[2] + shs[3];
        float tq = shq[0] + shq[1] + shq[2] + shq[3];
        float mean = ts * (1.0f / Dd);
        float var  = tq * (1.0f / Dd) - mean * mean;
        mr[0] = mean; mr[1] = rsqrtf(var + 1e-5f);
    }
    __syncthreads();
    float mean = mr[0], rstd = mr[1];
    float* yr = y + (size_t)t * Dd;
#pragma unroll
    for (int k = 0; k < 3; k++) {
        int d = tid + k * 128;
        yr[d] = (v[k] - mean) * rstd * g[d] + b[d];
    }
}

// ---------------- LayerNorm, one block (128 thr) per token ----------------
__global__ void ln_kernel(const float* __restrict__ x, float* __restrict__ y,
                          const float* __restrict__ g, const float* __restrict__ b) {
    int t = blockIdx.x;
    int tid = threadIdx.x;
    const float* xr = x + (size_t)t * Dd;
    float v0 = xr[tid], v1 = xr[tid + 128], v2 = xr[tid + 256];
    float s  = v0 + v1 + v2;
    float sq = v0*v0 + v1*v1 + v2*v2;
    s = warp_sum(s); sq = warp_sum(sq);
    __shared__ float shs[4], shq[4], mr[2];
    if ((tid & 31) == 0) { shs[tid >> 5] = s; shq[tid >> 5] = sq; }
    __syncthreads();
    if (tid == 0) {
        float ts = shs[0] + shs[1] + shs[2] + shs[3];
        float tq = shq[0] + shq[1] + shq[2] + shq[3];
        float mean = ts * (1.0f / Dd);
        float var  = tq * (1.0f / Dd) - mean * mean;
        mr[0] = mean; mr[1] = rsqrtf(var + 1e-5f);
    }
    __syncthreads();
    float mean = mr[0], rstd = mr[1];
    float* yr = y + (size_t)t * Dd;
    yr[tid]       = (v0 - mean) * rstd * g[tid]       + b[tid];
    yr[tid + 128] = (v1 - mean) * rstd * g[tid + 128] + b[tid + 128];
    yr[tid + 256] = (v2 - mean) * rstd * g[tid + 256] + b[tid + 256];
}

// ---------------- geglu: lin * gelu(pg); loc -> cat[:, :384], val -> V^T ---
__global__ void geglu_kernel(const float* __restrict__ h,
                             float* __restrict__ cat,
                             float* __restrict__ vt) {
    int t = blockIdx.x;
    int batch = t >> 11;          // /2048
    int sidx  = t & (Sq - 1);
    const float* hr = h + (size_t)t * Hd;
    for (int j = threadIdx.x; j < Ed; j += blockDim.x) {
        float lin = hr[2 * QKd + j];          // cols [96 : 864)
        float pg  = hr[2 * QKd + Ed + j];     // cols [864 : 1632)
        float gl  = 0.5f * pg * (1.0f + erff(pg * 0.70710678118654752f));
        float val = lin * gl;
        if (j < Dd) cat[(size_t)t * Ed + j] = val;                       // loc
        else        vt[((size_t)batch * Dd + (j - Dd)) * Sq + sidx] = val; // V^T
    }
}

// ---------------- causal row softmax over stored scores -------------------
__global__ void softmax_kernel(float* __restrict__ p) {
    int i = blockIdx.x;   // query row within batch
    int b = blockIdx.y;
    float* row = p + ((size_t)b * Sq + i) * Sq;
    int L = i + 1;
    int tid = threadIdx.x;   // 256 threads
    const float scale = 0.14433756729740643f;   // 1/sqrt(48)
    __shared__ float sh[8];

    float m = -3.0e38f;
    for (int j = tid; j < L; j += 256) m = fmaxf(m, row[j]);
    m = warp_max(m);
    if ((tid & 31) == 0) sh[tid >> 5] = m;
    __syncthreads();
    float mm = sh[0];
#pragma unroll
    for (int k = 1; k < 8; k++) mm = fmaxf(mm, sh[k]);
    __syncthreads();   // before reusing sh

    float sum = 0.0f;
    for (int j = tid; j < L; j += 256) {
        float e = __expf((row[j] - mm) * scale);
        row[j] = e;
        sum += e;
    }
    sum = warp_sum(sum);
    if ((tid & 31) == 0) sh[tid >> 5] = sum;
    __syncthreads();
    float tot = sh[0];
#pragma unroll
    for (int k = 1; k < 8; k++) tot += sh[k];
    float inv = 1.0f / tot;

    for (int j = tid; j < L; j += 256) row[j] *= inv;
    for (int j = L + tid; j < Sq; j += 256) row[j] = 0.0f;   // zero upper triangle
}

// ---------------- generic SGEMM: C = A(MxK) * B(NxK)^T, batched ------------
// 128x128 block tile, BK=8, 256 threads, 8x8 register micro-tile.
// M is always a multiple of 128 at our call sites; N is guarded.
template <bool ADD>
__global__ void __launch_bounds__(256, 2)
gemm_abt(const float* __restrict__ A, int lda, long long sA,
         const float* __restrict__ B, int ldb, long long sB,
         float* __restrict__ C, int ldc, long long sC,
         int M, int N, int K) {
    A += (long long)blockIdx.z * sA;
    B += (long long)blockIdx.z * sB;
    C += (long long)blockIdx.z * sC;
    int bm = blockIdx.y * 128;
    int bn = blockIdx.x * 128;

    __shared__ float As[8][128];
    __shared__ float Bs[8][128];

    int tid = threadIdx.x;
    int tx = tid & 15;   // 16 col groups * 8
    int ty = tid >> 4;   // 16 row groups * 8

    float acc[8][8] = {};

    int lrow = tid >> 1;            // 0..127
    int lkk  = (tid & 1) * 4;       // 0 or 4
    const float* Aptr = A + (size_t)(bm + lrow) * lda + lkk;
    bool bvalid = (bn + lrow) < N;
    const float* Bptr = B + (size_t)(bn + lrow) * ldb + lkk;

    for (int k0 = 0; k0 < K; k0 += 8) {
        float4 av = *reinterpret_cast<const float4*>(Aptr + k0);
        float4 bv = bvalid ? *reinterpret_cast<const float4*>(Bptr + k0)
                           : make_float4(0.f, 0.f, 0.f, 0.f);
        As[lkk + 0][lrow] = av.x; As[lkk + 1][lrow] = av.y;
        As[lkk + 2][lrow] = av.z; As[lkk + 3][lrow] = av.w;
        Bs[lkk + 0][lrow] = bv.x; Bs[lkk + 1][lrow] = bv.y;
        Bs[lkk + 2][lrow] = bv.z; Bs[lkk + 3][lrow] = bv.w;
        __syncthreads();
#pragma unroll
        for (int kk = 0; kk < 8; kk++) {
            float a[8], b[8];
            *reinterpret_cast<float4*>(&a[0]) = *reinterpret_cast<const float4*>(&As[kk][ty * 8]);
            *reinterpret_cast<float4*>(&a[4]) = *reinterpret_cast<const float4*>(&As[kk][ty * 8 + 4]);
            *reinterpret_cast<float4*>(&b[0]) = *reinterpret_cast<const float4*>(&Bs[kk][tx * 8]);
            *reinterpret_cast<float4*>(&b[4]) = *reinterpret_cast<const float4*>(&Bs[kk][tx * 8 + 4]);
#pragma unroll
            for (int i = 0; i < 8; i++)
#pragma unroll
                for (int j = 0; j < 8; j++)
                    acc[i][j] += a[i] * b[j];
        }
        __syncthreads();
    }

#pragma unroll
    for (int i = 0; i < 8; i++) {
        int m = bm + ty * 8 + i;
        float* Crow = C + (size_t)m * ldc;
#pragma unroll
        for (int j = 0; j < 8; j++) {
            int n = bn + tx * 8 + j;
            if (n < N) {
                if (ADD) Crow[n] += acc[i][j];
                else     Crow[n]  = acc[i][j];
            }
        }
    }
}

static inline void gemm(const float* A, int lda, long long sA,
                        const float* B, int ldb, long long sB,
                        float* C, int ldc, long long sC,
                        int M, int N, int K, int batch, bool add) {
    dim3 grid((N + 127) / 128, (M + 127) / 128, batch);
    if (add) gemm_abt<true ><<<grid, 256>>>(A, lda, sA, B, ldb, sB, C, ldc, sC, M, N, K);
    else     gemm_abt<false><<<grid, 256>>>(A, lda, sA, B, ldb, sB, C, ldc, sC, M, N, K);
}

// ---------------- driver ----------------
extern "C" void kernel_launch(void* const* d_in, const int* in_sizes, int n_in,
                              void* d_out, int out_size) {
    const int*   q      = (const int*)  d_in[0];
    const float* freqs  = (const float*)d_in[1];
    const float* exp_w  = (const float*)d_in[2];   // (8, 1632, 384)
    const float* proj_w = (const float*)d_in[3];   // (8, 384, 768)
    const float* blk_g  = (const float*)d_in[4];   // (8, 384)
    const float* blk_b  = (const float*)d_in[5];   // (8, 384)
    const float* ln_g   = (const float*)d_in[6];
    const float* ln_b   = (const float*)d_in[7];
    const float* out_w  = (const float*)d_in[8];   // (100, 384)
    float* out = (float*)d_out;

    float *x, *xn, *h, *cat, *vt, *p;
    cudaGetSymbolAddress((void**)&x,   g_x);
    cudaGetSymbolAddress((void**)&xn,  g_xn);
    cudaGetSymbolAddress((void**)&h,   g_h);
    cudaGetSymbolAddress((void**)&cat, g_cat);
    cudaGetSymbolAddress((void**)&vt,  g_vt);
    cudaGetSymbolAddress((void**)&p,   g_p);

    // x = LN(concat(sin, cos))
    embed_ln_kernel<<<Tq, 128>>>(q, freqs, ln_g, ln_b, x);

    for (int blk = 0; blk < NBq; blk++) {
        // xn = LN(x, blk_g[blk], blk_b[blk])
        ln_kernel<<<Tq, 128>>>(x, xn, blk_g + blk * Dd, blk_b + blk * Dd);

        // h = xn @ exp_w[blk]^T   (8192 x 1632, K=384)
        gemm(xn, Dd, 0,
             exp_w + (size_t)blk * Hd * Dd, Dd, 0,
             h, Hd, 0,
             Tq, Hd, Dd, 1, false);

        // geglu -> cat[:, :384] (loc), g_vt (V transposed per batch)
        geglu_kernel<<<Tq, 256>>>(h, cat, vt);

        // scores: per batch, qh (2048x48) @ kh^T (2048x48)  -> p (2048x2048)
        gemm(h,       Hd, (long long)Sq * Hd,
             h + QKd, Hd, (long long)Sq * Hd,
             p, Sq, (long long)Sq * Sq,
             Sq, Sq, QKd, Bq, false);

        // causal softmax (scale applied here), zero upper triangle
        softmax_kernel<<<dim3(Sq, Bq), 256>>>(p);

        // attn = P (2048x2048) @ Vt^T (384x2048) -> cat[:, 384:768]
        gemm(p,  Sq, (long long)Sq * Sq,
             vt, Sq, (long long)Dd * Sq,
             cat + Dd, Ed, (long long)Sq * Ed,
             Sq, Dd, Sq, Bq, false);

        // x += cat (8192x768) @ proj_w[blk]^T (384x768)
        gemm(cat, Ed, 0,
             proj_w + (size_t)blk * Dd * Ed, Ed, 0,
             x, Dd, 0,
             Tq, Dd, Ed, 1, true);
    }

    // final LN + logits
    ln_kernel<<<Tq, 128>>>(x, xn, ln_g, ln_b);
    gemm(xn, Dd, 0,
         out_w, Dd, 0,
         out, VOCABq, 0,
         Tq, VOCABq, Dd, 1, false);
}

// round 6
// speedup vs baseline: 1.1510x; 1.1510x over previous
#include <cuda_runtime.h>

// ---------------- problem constants ----------------
#define Bq      4
#define Sq      2048
#define Tq      (Bq * Sq)      // 8192 tokens
#define Dd      384
#define QKd     48
#define Ed      768
#define Hd      1632           // 2*QK + 2*E
#define NBq     8
#define VOCABq  100

// ---------------- scratch (static device globals; no cudaMalloc allowed) ----
__device__ float g_x[Tq * Dd];                       // residual stream
__device__ float g_xn[Tq * Dd];                      // LN output
__device__ float g_h[(size_t)Tq * Hd];               // block GEMM out (53.5 MB)
__device__ float g_cat[(size_t)Tq * Ed];             // [loc | attn]
__device__ float g_v[(size_t)Tq * Dd];               // V, row-major [t, d]
__device__ float g_p[(size_t)Bq * Sq * Sq];          // attention probs (67 MB)

// ---------------- small helpers ----------------
__device__ __forceinline__ float warp_sum(float v) {
#pragma unroll
    for (int o = 16; o; o >>= 1) v += __shfl_xor_sync(0xffffffffu, v, o);
    return v;
}
__device__ __forceinline__ float warp_max(float v) {
#pragma unroll
    for (int o = 16; o; o >>= 1) v = fmaxf(v, __shfl_xor_sync(0xffffffffu, v, o));
    return v;
}

// ---------------- embed (sin/cos) + LayerNorm, one block per token ---------
__global__ void embed_ln_kernel(const int* __restrict__ q,
                                const float* __restrict__ freqs,
                                const float* __restrict__ g,
                                const float* __restrict__ b,
                                float* __restrict__ y) {
    int t = blockIdx.x;
    int tid = threadIdx.x;   // 128 threads, 3 dims each
    float qv = (float)q[t];
    float v[3];
#pragma unroll
    for (int k = 0; k < 3; k++) {
        int d = tid + k * 128;
        float ang;
        if (d < Dd / 2) { ang = qv * freqs[d];          v[k] = sinf(ang); }
        else            { ang = qv * freqs[d - Dd / 2]; v[k] = cosf(ang); }
    }
    float s = v[0] + v[1] + v[2];
    float sq = v[0]*v[0] + v[1]*v[1] + v[2]*v[2];
    s = warp_sum(s); sq = warp_sum(sq);
    __shared__ float shs[4], shq[4], mr[2];
    if ((tid & 31) == 0) { shs[tid >> 5] = s; shq[tid >> 5] = sq; }
    __syncthreads();
    if (tid == 0) {
        float ts = shs[0] + shs[1] + shs[2] + shs[3];
        float tq = shq[0] + shq[1] + shq[2] + shq[3];
        float mean = ts * (1.0f / Dd);
        float var  = tq * (1.0f / Dd) - mean * mean;
        mr[0] = mean; mr[1] = rsqrtf(var + 1e-5f);
    }
    __syncthreads();
    float mean = mr[0], rstd = mr[1];
    float* yr = y + (size_t)t * Dd;
#pragma unroll
    for (int k = 0; k < 3; k++) {
        int d = tid + k * 128;
        yr[d] = (v[k] - mean) * rstd * g[d] + b[d];
    }
}

// ---------------- LayerNorm, one block (128 thr) per token ----------------
__global__ void ln_kernel(const float* __restrict__ x, float* __restrict__ y,
                          const float* __restrict__ g, const float* __restrict__ b) {
    int t = blockIdx.x;
    int tid = threadIdx.x;
    const float* xr = x + (size_t)t * Dd;
    float v0 = xr[tid], v1 = xr[tid + 128], v2 = xr[tid + 256];
    float s  = v0 + v1 + v2;
    float sq = v0*v0 + v1*v1 + v2*v2;
    s = warp_sum(s); sq = warp_sum(sq);
    __shared__ float shs[4], shq[4], mr[2];
    if ((tid & 31) == 0) { shs[tid >> 5] = s; shq[tid >> 5] = sq; }
    __syncthreads();
    if (tid == 0) {
        float ts = shs[0] + shs[1] + shs[2] + shs[3];
        float tq = shq[0] + shq[1] + shq[2] + shq[3];
        float mean = ts * (1.0f / Dd);
        float var  = tq * (1.0f / Dd) - mean * mean;
        mr[0] = mean; mr[1] = rsqrtf(var + 1e-5f);
    }
    __syncthreads();
    float mean = mr[0], rstd = mr[1];
    float* yr = y + (size_t)t * Dd;
    yr[tid]       = (v0 - mean) * rstd * g[tid]       + b[tid];
    yr[tid + 128] = (v1 - mean) * rstd * g[tid + 128] + b[tid + 128];
    yr[tid + 256] = (v2 - mean) * rstd * g[tid + 256] + b[tid + 256];
}

// ---------------- geglu: lin * gelu(pg); loc -> cat[:, :384], val -> V -----
// Fully vectorized float4, coalesced (V stored row-major now). 192 threads.
__global__ void geglu_kernel(const float* __restrict__ h,
                             float* __restrict__ cat,
                             float* __restrict__ v) {
    int t = blockIdx.x;
    int j4 = threadIdx.x;   // 0..191, 4 cols each
    const float* hr = h + (size_t)t * Hd;
    float4 lin = *reinterpret_cast<const float4*>(hr + 2 * QKd + j4 * 4);
    float4 pg  = *reinterpret_cast<const float4*>(hr + 2 * QKd + Ed + j4 * 4);
    float4 r;
    r.x = lin.x * 0.5f * pg.x * (1.0f + erff(pg.x * 0.70710678118654752f));
    r.y = lin.y * 0.5f * pg.y * (1.0f + erff(pg.y * 0.70710678118654752f));
    r.z = lin.z * 0.5f * pg.z * (1.0f + erff(pg.z * 0.70710678118654752f));
    r.w = lin.w * 0.5f * pg.w * (1.0f + erff(pg.w * 0.70710678118654752f));
    if (j4 < 96) *reinterpret_cast<float4*>(cat + (size_t)t * Ed + j4 * 4) = r;
    else         *reinterpret_cast<float4*>(v + (size_t)t * Dd + (j4 - 96) * 4) = r;
}

// ---------------- causal row softmax over stored scores -------------------
// Zero-fill only up to the end of the diagonal 128-block (P beyond that is
// never read: the P@V GEMM caps its K-loop at the diagonal block boundary).
__global__ void softmax_kernel(float* __restrict__ p) {
    int i = blockIdx.x;   // query row within batch
    int b = blockIdx.y;
    float* row = p + ((size_t)b * Sq + i) * Sq;
    int L = i + 1;
    int zend = ((i >> 7) + 1) << 7;   // end of diagonal 128-block
    int tid = threadIdx.x;   // 256 threads
    const float scale = 0.14433756729740643f;   // 1/sqrt(48)
    __shared__ float sh[8];

    float m = -3.0e38f;
    for (int j = tid; j < L; j += 256) m = fmaxf(m, row[j]);
    m = warp_max(m);
    if ((tid & 31) == 0) sh[tid >> 5] = m;
    __syncthreads();
    float mm = sh[0];
#pragma unroll
    for (int k = 1; k < 8; k++) mm = fmaxf(mm, sh[k]);
    __syncthreads();

    float sum = 0.0f;
    for (int j = tid; j < L; j += 256) {
        float e = __expf((row[j] - mm) * scale);
        row[j] = e;
        sum += e;
    }
    sum = warp_sum(sum);
    if ((tid & 31) == 0) sh[tid >> 5] = sum;
    __syncthreads();
    float tot = sh[0];
#pragma unroll
    for (int k = 1; k < 8; k++) tot += sh[k];
    float inv = 1.0f / tot;

    for (int j = tid; j < L; j += 256) row[j] *= inv;
    for (int j = L + tid; j < zend; j += 256) row[j] = 0.0f;
}

// ---------------- double-buffered SGEMM --------------------------------
// BT=true : C = A(MxK) * B(NxK)^T     (both row-major, K contiguous)
// BT=false: C = A(MxK) * B(KxN)       (B row-major, N contiguous)
// 128x128 tile, BK=8, 256 threads, 8x8 micro-tile, 2-deep smem pipeline.
// causal: 0=none, 1=skip tiles with bn>bm (scores), 2=cap K at bm+128 (P@V).
// M is a multiple of 128 at all call sites; N guarded.
template <bool ADD, bool BT>
__global__ void __launch_bounds__(256, 2)
gemm_k(const float* __restrict__ A, int lda, long long sA,
       const float* __restrict__ B, int ldb, long long sB,
       float* __restrict__ C, int ldc, long long sC,
       int M, int N, int K, int causal) {
    int bm = blockIdx.y * 128;
    int bn = blockIdx.x * 128;
    if (causal == 1 && bn > bm) return;
    int Keff = (causal == 2) ? ((bm + 128 < K) ? bm + 128 : K) : K;

    A += (long long)blockIdx.z * sA;
    B += (long long)blockIdx.z * sB;
    C += (long long)blockIdx.z * sC;

    __shared__ float As[2][8][128];
    __shared__ float Bs[2][8][128];

    int tid = threadIdx.x;
    int tx = tid & 15, ty = tid >> 4;

    // A load lanes: 128 rows x (2 threads * float4) covering BK=8
    int arow = tid >> 1;
    int akk  = (tid & 1) * 4;
    const float* Ap = A + (size_t)(bm + arow) * lda + akk;

    // B load lanes
    int brow = 0, bkk = 0, bcol = 0;
    bool bval;
    const float* Bp;
    if (BT) {
        brow = arow; bkk = akk;
        bval = (bn + brow) < N;
        Bp = B + (size_t)(bn + brow) * ldb + bkk;
    } else {
        bkk  = tid >> 5;          // 0..7
        bcol = (tid & 31) * 4;    // 0..124
        bval = (bn + bcol) < N;
        Bp = B + (size_t)bkk * ldb + bn + bcol;
    }

    float4 av, bv;
    float acc[8][8] = {};

    // prologue: tile 0
    av = *reinterpret_cast<const float4*>(Ap);
    if (BT) bv = bval ? *reinterpret_cast<const float4*>(Bp) : make_float4(0.f,0.f,0.f,0.f);
    else    bv = bval ? *reinterpret_cast<const float4*>(Bp) : make_float4(0.f,0.f,0.f,0.f);
    As[0][akk+0][arow]=av.x; As[0][akk+1][arow]=av.y;
    As[0][akk+2][arow]=av.z; As[0][akk+3][arow]=av.w;
    if (BT) {
        Bs[0][bkk+0][brow]=bv.x; Bs[0][bkk+1][brow]=bv.y;
        Bs[0][bkk+2][brow]=bv.z; Bs[0][bkk+3][brow]=bv.w;
    } else {
        *reinterpret_cast<float4*>(&Bs[0][bkk][bcol]) = bv;
    }
    __syncthreads();

    int buf = 0;
    for (int k0 = 0; k0 < Keff; k0 += 8) {
        bool has_next = (k0 + 8) < Keff;
        if (has_next) {
            av = *reinterpret_cast<const float4*>(Ap + k0 + 8);
            if (BT) bv = bval ? *reinterpret_cast<const float4*>(Bp + k0 + 8)
                              : make_float4(0.f,0.f,0.f,0.f);
            else    bv = bval ? *reinterpret_cast<const float4*>(Bp + (size_t)(k0 + 8) * ldb)
                              : make_float4(0.f,0.f,0.f,0.f);
        }
#pragma unroll
        for (int kk = 0; kk < 8; kk++) {
            float a[8], b[8];
            *reinterpret_cast<float4*>(&a[0]) = *reinterpret_cast<const float4*>(&As[buf][kk][ty*8]);
            *reinterpret_cast<float4*>(&a[4]) = *reinterpret_cast<const float4*>(&As[buf][kk][ty*8+4]);
            *reinterpret_cast<float4*>(&b[0]) = *reinterpret_cast<const float4*>(&Bs[buf][kk][tx*8]);
            *reinterpret_cast<float4*>(&b[4]) = *reinterpret_cast<const float4*>(&Bs[buf][kk][tx*8+4]);
#pragma unroll
            for (int i = 0; i < 8; i++)
#pragma unroll
                for (int j = 0; j < 8; j++)
                    acc[i][j] += a[i] * b[j];
        }
        if (has_next) {
            int nb = buf ^ 1;
            As[nb][akk+0][arow]=av.x; As[nb][akk+1][arow]=av.y;
            As[nb][akk+2][arow]=av.z; As[nb][akk+3][arow]=av.w;
            if (BT) {
                Bs[nb][bkk+0][brow]=bv.x; Bs[nb][bkk+1][brow]=bv.y;
                Bs[nb][bkk+2][brow]=bv.z; Bs[nb][bkk+3][brow]=bv.w;
            } else {
                *reinterpret_cast<float4*>(&Bs[nb][bkk][bcol]) = bv;
            }
            __syncthreads();
            buf = nb;
        }
    }

    // epilogue
    if (bn + 128 <= N) {
#pragma unroll
        for (int i = 0; i < 8; i++) {
            float* Crow = C + (size_t)(bm + ty * 8 + i) * ldc + bn + tx * 8;
            if (ADD) {
                float4 c0 = *reinterpret_cast<float4*>(Crow);
                float4 c1 = *reinterpret_cast<float4*>(Crow + 4);
                c0.x += acc[i][0]; c0.y += acc[i][1]; c0.z += acc[i][2]; c0.w += acc[i][3];
                c1.x += acc[i][4]; c1.y += acc[i][5]; c1.z += acc[i][6]; c1.w += acc[i][7];
                *reinterpret_cast<float4*>(Crow)     = c0;
                *reinterpret_cast<float4*>(Crow + 4) = c1;
            } else {
                *reinterpret_cast<float4*>(Crow)     = make_float4(acc[i][0], acc[i][1], acc[i][2], acc[i][3]);
                *reinterpret_cast<float4*>(Crow + 4) = make_float4(acc[i][4], acc[i][5], acc[i][6], acc[i][7]);
            }
        }
    } else {
#pragma unroll
        for (int i = 0; i < 8; i++) {
            float* Crow = C + (size_t)(bm + ty * 8 + i) * ldc;
#pragma unroll
            for (int j = 0; j < 8; j++) {
                int n = bn + tx * 8 + j;
                if (n < N) {
                    if (ADD) Crow[n] += acc[i][j];
                    else     Crow[n]  = acc[i][j];
                }
            }
        }
    }
}

static inline void gemm(const float* A, int lda, long long sA,
                        const float* B, int ldb, long long sB,
                        float* C, int ldc, long long sC,
                        int M, int N, int K, int batch,
                        bool add, bool bt, int causal) {
    dim3 grid((N + 127) / 128, (M + 127) / 128, batch);
    if (bt) {
        if (add) gemm_k<true , true ><<<grid, 256>>>(A, lda, sA, B, ldb, sB, C, ldc, sC, M, N, K, causal);
        else     gemm_k<false, true ><<<grid, 256>>>(A, lda, sA, B, ldb, sB, C, ldc, sC, M, N, K, causal);
    } else {
        if (add) gemm_k<true , false><<<grid, 256>>>(A, lda, sA, B, ldb, sB, C, ldc, sC, M, N, K, causal);
        else     gemm_k<false, false><<<grid, 256>>>(A, lda, sA, B, ldb, sB, C, ldc, sC, M, N, K, causal);
    }
}

// ---------------- driver ----------------
extern "C" void kernel_launch(void* const* d_in, const int* in_sizes, int n_in,
                              void* d_out, int out_size) {
    const int*   q      = (const int*)  d_in[0];
    const float* freqs  = (const float*)d_in[1];
    const float* exp_w  = (const float*)d_in[2];   // (8, 1632, 384)
    const float* proj_w = (const float*)d_in[3];   // (8, 384, 768)
    const float* blk_g  = (const float*)d_in[4];   // (8, 384)
    const float* blk_b  = (const float*)d_in[5];   // (8, 384)
    const float* ln_g   = (const float*)d_in[6];
    const float* ln_b   = (const float*)d_in[7];
    const float* out_w  = (const float*)d_in[8];   // (100, 384)
    float* out = (float*)d_out;

    float *x, *xn, *h, *cat, *v, *p;
    cudaGetSymbolAddress((void**)&x,   g_x);
    cudaGetSymbolAddress((void**)&xn,  g_xn);
    cudaGetSymbolAddress((void**)&h,   g_h);
    cudaGetSymbolAddress((void**)&cat, g_cat);
    cudaGetSymbolAddress((void**)&v,   g_v);
    cudaGetSymbolAddress((void**)&p,   g_p);

    // x = LN(concat(sin, cos))
    embed_ln_kernel<<<Tq, 128>>>(q, freqs, ln_g, ln_b, x);

    for (int blk = 0; blk < NBq; blk++) {
        // xn = LN(x, blk_g[blk], blk_b[blk])
        ln_kernel<<<Tq, 128>>>(x, xn, blk_g + blk * Dd, blk_b + blk * Dd);

        // h = xn @ exp_w[blk]^T   (8192 x 1632, K=384)
        gemm(xn, Dd, 0,
             exp_w + (size_t)blk * Hd * Dd, Dd, 0,
             h, Hd, 0,
             Tq, Hd, Dd, 1, false, true, 0);

        // geglu -> cat[:, :384] (loc), g_v row-major (val)
        geglu_kernel<<<Tq, 192>>>(h, cat, v);

        // scores: per batch, qh (2048x48) @ kh^T; skip tiles above diagonal
        gemm(h,       Hd, (long long)Sq * Hd,
             h + QKd, Hd, (long long)Sq * Hd,
             p, Sq, (long long)Sq * Sq,
             Sq, Sq, QKd, Bq, false, true, 1);

        // causal softmax (scale applied here), zero intra-diagonal-block tail
        softmax_kernel<<<dim3(Sq, Bq), 256>>>(p);

        // attn = P (2048x2048) @ V (2048x384) -> cat[:, 384:768]; K capped causally
        gemm(p, Sq, (long long)Sq * Sq,
             v, Dd, (long long)Sq * Dd,
             cat + Dd, Ed, (long long)Sq * Ed,
             Sq, Dd, Sq, Bq, false, false, 2);

        // x += cat (8192x768) @ proj_w[blk]^T (384x768)
        gemm(cat, Ed, 0,
             proj_w + (size_t)blk * Dd * Ed, Ed, 0,
             x, Dd, 0,
             Tq, Dd, Ed, 1, true, true, 0);
    }

    // final LN + logits
    ln_kernel<<<Tq, 128>>>(x, xn, ln_g, ln_b);
    gemm(xn, Dd, 0,
         out_w, Dd, 0,
         out, VOCABq, 0,
         Tq, VOCABq, Dd, 1, false, true, 0);
}

// round 8
// speedup vs baseline: 2.2234x; 1.9317x over previous
#include <cuda_runtime.h>
#include <cuda_bf16.h>
#include <cstdint>

// ---------------- problem constants ----------------
#define Bq      4
#define Sq      2048
#define Tq      (Bq * Sq)      // 8192 tokens
#define Dd      384
#define QKd     48
#define Ed      768
#define Hd      1632           // 2*QK + 2*E
#define NBq     8
#define VOCABq  100

// ---------------- scratch (static device globals; no cudaMalloc allowed) ----
__device__ float g_x[Tq * Dd];                       // residual stream
__device__ float g_xn[Tq * Dd];                      // LN output
__device__ float g_h[(size_t)Tq * Hd];               // block GEMM out (53.5 MB)
__device__ float g_cat[(size_t)Tq * Ed];             // [loc | attn]
__device__ float g_v[(size_t)Tq * Dd];               // V, row-major [t, d]
__device__ float g_vt[(size_t)Bq * Dd * Sq];         // V^T per batch [d, s]
__device__ float g_p[(size_t)Bq * Sq * Sq];          // attention probs (67 MB)

// ================= low-level helpers =================
__device__ __forceinline__ uint32_t s2u(const void* p) {
    uint32_t a;
    asm("{ .reg .u64 t; cvta.to.shared.u64 t, %1; cvt.u32.u64 %0, t; }" : "=r"(a) : "l"(p));
    return a;
}
__device__ __forceinline__ void sts128(uint32_t addr, uint4 v) {
    asm volatile("st.shared.v4.b32 [%0], {%1, %2, %3, %4};"
                 :: "r"(addr), "r"(v.x), "r"(v.y), "r"(v.z), "r"(v.w) : "memory");
}
// XOR swizzle within a 128B row: unit u (16B) -> u ^ (row & 7). Bijective per
// row; makes ldmatrix (8 rows, same unit) hit 8 distinct 16B columns.
__device__ __forceinline__ uint32_t swz(uint32_t off) { return off ^ ((off >> 3) & 0x70); }

__device__ __forceinline__ void ldm_x4(uint32_t addr, uint32_t* r) {
    asm volatile("ldmatrix.sync.aligned.m8n8.x4.shared.b16 {%0,%1,%2,%3}, [%4];"
                 : "=r"(r[0]), "=r"(r[1]), "=r"(r[2]), "=r"(r[3]) : "r"(addr));
}
__device__ __forceinline__ void mma16816(float* c, const uint32_t* a, const uint32_t* b) {
    asm volatile("mma.sync.aligned.m16n8k16.row.col.f32.bf16.bf16.f32 "
                 "{%0,%1,%2,%3}, {%4,%5,%6,%7}, {%8,%9}, {%0,%1,%2,%3};"
                 : "+f"(c[0]), "+f"(c[1]), "+f"(c[2]), "+f"(c[3])
                 : "r"(a[0]), "r"(a[1]), "r"(a[2]), "r"(a[3]), "r"(b[0]), "r"(b[1]));
}

// split 8 floats into packed bf16x2 hi/lo halves (a = hi + lo)
__device__ __forceinline__ void split8(float4 x0, float4 x1, uint4& hi, uint4& lo) {
    float v[8] = {x0.x, x0.y, x0.z, x0.w, x1.x, x1.y, x1.z, x1.w};
    uint32_t h[4], l[4];
#pragma unroll
    for (int i = 0; i < 4; i++) {
        float a = v[2*i], b = v[2*i+1];
        __nv_bfloat162 hh = __floats2bfloat162_rn(a, b);
        float ra = a - __bfloat162float(hh.x);
        float rb = b - __bfloat162float(hh.y);
        __nv_bfloat162 ll = __floats2bfloat162_rn(ra, rb);
        h[i] = *reinterpret_cast<uint32_t*>(&hh);
        l[i] = *reinterpret_cast<uint32_t*>(&ll);
    }
    hi = make_uint4(h[0], h[1], h[2], h[3]);
    lo = make_uint4(l[0], l[1], l[2], l[3]);
}

// ================= HMMA GEMM: C = A(MxK) * B(NxK)^T, 3x-bf16 split =========
// 128x128 CTA tile, BK=64, 8 warps (2x4), reg accumulators, single smem buf.
// causal: 0=none, 1=skip tiles bn>bm (scores), 2=cap K at bm+128 (P@V).
#define TILE_B   16384                 // 128 rows x 64 bf16 = 128B/row
#define SHM_MMA  (4 * TILE_B + 128)    // Ah, Al, Bh, Bl + align slack

template <bool ADD>
__global__ void __launch_bounds__(256, 2)
gemm_mma(const float* __restrict__ A, int lda, long long sA,
         const float* __restrict__ B, int ldb, long long sB,
         float* __restrict__ C, int ldc, long long sC,
         int N, int K, int causal) {
    int bm = blockIdx.y * 128;
    int bn = blockIdx.x * 128;
    if (causal == 1 && bn > bm) return;
    int Keff = (causal == 2) ? ((bm + 128 < K) ? bm + 128 : K) : K;
    int nchunks = (Keff + 63) >> 6;

    A += (long long)blockIdx.z * sA;
    B += (long long)blockIdx.z * sB;
    C += (long long)blockIdx.z * sC;

    extern __shared__ char dsm[];
    uint32_t base = (s2u(dsm) + 127u) & ~127u;
    uint32_t Ah = base, Al = base + TILE_B, Bh = base + 2*TILE_B, Bl = base + 3*TILE_B;

    int tid  = threadIdx.x;
    int wid  = tid >> 5, lane = tid & 31;
    int m0w  = (wid >> 2) * 64;     // warp M offset (2 warps in M)
    int n0w  = (wid & 3) * 32;      // warp N offset (4 warps in N)

    // loader lanes: row r (0..127), 4 16B-units starting at u0
    int r  = tid >> 1;
    int u0 = (tid & 1) * 4;
    uint32_t rowoff = (uint32_t)r * 128u;
    const float4* Ar4 = reinterpret_cast<const float4*>(A + (size_t)(bm + r) * lda);
    bool bok = (bn + r) < N;
    const float4* Br4 = reinterpret_cast<const float4*>(B + (size_t)(bn + r) * ldb);

    float acc[4][4][4];
#pragma unroll
    for (int i = 0; i < 4; i++)
#pragma unroll
        for (int j = 0; j < 4; j++)
#pragma unroll
            for (int e = 0; e < 4; e++) acc[i][j][e] = 0.0f;

    // ldmatrix per-lane addressing (tile-relative), see fragment layout notes:
    // A m16k16 tile: row = (lane&15), unit byte = (lane>>4)*16
    // B n16k16 pair: row = ((lane>>4)<<3) + (lane&7), unit byte = ((lane>>3)&1)*16
    uint32_t a_row  = (uint32_t)(lane & 15);
    uint32_t a_colb = (uint32_t)((lane >> 4) * 16);
    uint32_t b_row  = (uint32_t)(((lane >> 4) << 3) + (lane & 7));
    uint32_t b_colb = (uint32_t)(((lane >> 3) & 1) * 16);

    for (int ch = 0; ch < nchunks; ch++) {
        int k0 = ch << 6;
        __syncthreads();   // previous compute done before overwrite
#pragma unroll
        for (int uu = 0; uu < 4; uu++) {
            int u  = u0 + uu;
            int kb = k0 + u * 8;
            uint32_t soff = swz(rowoff + (uint32_t)u * 16u);
            float4 z = make_float4(0.f, 0.f, 0.f, 0.f);
            float4 a0 = z, a1 = z;
            if (kb < K) { a0 = Ar4[kb >> 2]; a1 = Ar4[(kb >> 2) + 1]; }
            uint4 hi, lo;
            split8(a0, a1, hi, lo);
            sts128(Ah + soff, hi); sts128(Al + soff, lo);
            float4 b0 = z, b1 = z;
            if (bok && kb < K) { b0 = Br4[kb >> 2]; b1 = Br4[(kb >> 2) + 1]; }
            split8(b0, b1, hi, lo);
            sts128(Bh + soff, hi); sts128(Bl + soff, lo);
        }
        __syncthreads();

#pragma unroll
        for (int ks = 0; ks < 4; ks++) {
            uint32_t kbyte = (uint32_t)ks * 32u;
            uint32_t afrag[4][4], bhfrag[2][4], blfrag[2][4];
#pragma unroll
            for (int mt = 0; mt < 4; mt++) {
                uint32_t rr = (uint32_t)(m0w + mt * 16) + a_row;
                ldm_x4(Ah + swz(rr * 128u + kbyte + a_colb), afrag[mt]);
            }
#pragma unroll
            for (int bt = 0; bt < 2; bt++) {
                uint32_t rr = (uint32_t)(n0w + bt * 16) + b_row;
                uint32_t off = swz(rr * 128u + kbyte + b_colb);
                ldm_x4(Bh + off, bhfrag[bt]);
                ldm_x4(Bl + off, blfrag[bt]);
            }
            // terms 1 & 2: Ahi*Bhi + Ahi*Blo
#pragma unroll
            for (int mt = 0; mt < 4; mt++)
#pragma unroll
                for (int nt = 0; nt < 4; nt++) {
                    mma16816(acc[mt][nt], afrag[mt], &bhfrag[nt >> 1][(nt & 1) * 2]);
                    mma16816(acc[mt][nt], afrag[mt], &blfrag[nt >> 1][(nt & 1) * 2]);
                }
            // term 3: Alo*Bhi (reuse afrag regs)
#pragma unroll
            for (int mt = 0; mt < 4; mt++) {
                uint32_t rr = (uint32_t)(m0w + mt * 16) + a_row;
                ldm_x4(Al + swz(rr * 128u + kbyte + a_colb), afrag[mt]);
            }
#pragma unroll
            for (int mt = 0; mt < 4; mt++)
#pragma unroll
                for (int nt = 0; nt < 4; nt++)
                    mma16816(acc[mt][nt], afrag[mt], &bhfrag[nt >> 1][(nt & 1) * 2]);
        }
    }

    // epilogue: c0,c1 -> (row, col),(row, col+1); c2,c3 -> row+8
#pragma unroll
    for (int mt = 0; mt < 4; mt++) {
        int row0 = bm + m0w + mt * 16 + (lane >> 2);
#pragma unroll
        for (int nt = 0; nt < 4; nt++) {
            int col = bn + n0w + nt * 8 + (lane & 3) * 2;
            float* c = acc[mt][nt];
#pragma unroll
            for (int half = 0; half < 2; half++) {
                float* Crow = C + (size_t)(row0 + half * 8) * ldc;
                float v0 = c[half * 2], v1 = c[half * 2 + 1];
                if (col + 1 < N) {
                    float2 cv;
                    if (ADD) {
                        cv = *reinterpret_cast<float2*>(Crow + col);
                        cv.x += v0; cv.y += v1;
                    } else cv = make_float2(v0, v1);
                    *reinterpret_cast<float2*>(Crow + col) = cv;
                } else if (col < N) {
                    Crow[col] = ADD ? (Crow[col] + v0) : v0;
                }
            }
        }
    }
}

static inline void gemm_mma_launch(const float* A, int lda, long long sA,
                                   const float* B, int ldb, long long sB,
                                   float* C, int ldc, long long sC,
                                   int M, int N, int K, int batch,
                                   bool add, int causal) {
    dim3 grid((N + 127) / 128, M / 128, batch);
    if (add) {
        cudaFuncSetAttribute(gemm_mma<true>,  cudaFuncAttributeMaxDynamicSharedMemorySize, SHM_MMA);
        gemm_mma<true><<<grid, 256, SHM_MMA>>>(A, lda, sA, B, ldb, sB, C, ldc, sC, N, K, causal);
    } else {
        cudaFuncSetAttribute(gemm_mma<false>, cudaFuncAttributeMaxDynamicSharedMemorySize, SHM_MMA);
        gemm_mma<false><<<grid, 256, SHM_MMA>>>(A, lda, sA, B, ldb, sB, C, ldc, sC, N, K, causal);
    }
}

// ---------------- small helpers ----------------
__device__ __forceinline__ float warp_sum(float v) {
#pragma unroll
    for (int o = 16; o; o >>= 1) v += __shfl_xor_sync(0xffffffffu, v, o);
    return v;
}
__device__ __forceinline__ float warp_max(float v) {
#pragma unroll
    for (int o = 16; o; o >>= 1) v = fmaxf(v, __shfl_xor_sync(0xffffffffu, v, o));
    return v;
}

// ---------------- embed (sin/cos) + LayerNorm ----------------
__global__ void embed_ln_kernel(const int* __restrict__ q,
                                const float* __restrict__ freqs,
                                const float* __restrict__ g,
                                const float* __restrict__ b,
                                float* __restrict__ y) {
    int t = blockIdx.x;
    int tid = threadIdx.x;
    float qv = (float)q[t];
    float v[3];
#pragma unroll
    for (int k = 0; k < 3; k++) {
        int d = tid + k * 128;
        if (d < Dd / 2) v[k] = sinf(qv * freqs[d]);
        else            v[k] = cosf(qv * freqs[d - Dd / 2]);
    }
    float s = v[0] + v[1] + v[2];
    float sq = v[0]*v[0] + v[1]*v[1] + v[2]*v[2];
    s = warp_sum(s); sq = warp_sum(sq);
    __shared__ float shs[4], shq[4], mr[2];
    if ((tid & 31) == 0) { shs[tid >> 5] = s; shq[tid >> 5] = sq; }
    __syncthreads();
    if (tid == 0) {
        float ts = shs[0]+shs[1]+shs[2]+shs[3], tq = shq[0]+shq[1]+shq[2]+shq[3];
        float mean = ts * (1.0f / Dd);
        float var  = tq * (1.0f / Dd) - mean * mean;
        mr[0] = mean; mr[1] = rsqrtf(var + 1e-5f);
    }
    __syncthreads();
    float mean = mr[0], rstd = mr[1];
    float* yr = y + (size_t)t * Dd;
#pragma unroll
    for (int k = 0; k < 3; k++) {
        int d = tid + k * 128;
        yr[d] = (v[k] - mean) * rstd * g[d] + b[d];
    }
}

// ---------------- LayerNorm ----------------
__global__ void ln_kernel(const float* __restrict__ x, float* __restrict__ y,
                          const float* __restrict__ g, const float* __restrict__ b) {
    int t = blockIdx.x;
    int tid = threadIdx.x;
    const float* xr = x + (size_t)t * Dd;
    float v0 = xr[tid], v1 = xr[tid + 128], v2 = xr[tid + 256];
    float s  = v0 + v1 + v2;
    float sq = v0*v0 + v1*v1 + v2*v2;
    s = warp_sum(s); sq = warp_sum(sq);
    __shared__ float shs[4], shq[4], mr[2];
    if ((tid & 31) == 0) { shs[tid >> 5] = s; shq[tid >> 5] = sq; }
    __syncthreads();
    if (tid == 0) {
        float ts = shs[0]+shs[1]+shs[2]+shs[3], tq = shq[0]+shq[1]+shq[2]+shq[3];
        float mean = ts * (1.0f / Dd);
        float var  = tq * (1.0f / Dd) - mean * mean;
        mr[0] = mean; mr[1] = rsqrtf(var + 1e-5f);
    }
    __syncthreads();
    float mean = mr[0], rstd = mr[1];
    float* yr = y + (size_t)t * Dd;
    yr[tid]       = (v0 - mean) * rstd * g[tid]       + b[tid];
    yr[tid + 128] = (v1 - mean) * rstd * g[tid + 128] + b[tid + 128];
    yr[tid + 256] = (v2 - mean) * rstd * g[tid + 256] + b[tid + 256];
}

// ---------------- geglu ----------------
__global__ void geglu_kernel(const float* __restrict__ h,
                             float* __restrict__ cat,
                             float* __restrict__ v) {
    int t = blockIdx.x;
    int j4 = threadIdx.x;
    const float* hr = h + (size_t)t * Hd;
    float4 lin = *reinterpret_cast<const float4*>(hr + 2 * QKd + j4 * 4);
    float4 pg  = *reinterpret_cast<const float4*>(hr + 2 * QKd + Ed + j4 * 4);
    float4 rr;
    rr.x = lin.x * 0.5f * pg.x * (1.0f + erff(pg.x * 0.70710678118654752f));
    rr.y = lin.y * 0.5f * pg.y * (1.0f + erff(pg.y * 0.70710678118654752f));
    rr.z = lin.z * 0.5f * pg.z * (1.0f + erff(pg.z * 0.70710678118654752f));
    rr.w = lin.w * 0.5f * pg.w * (1.0f + erff(pg.w * 0.70710678118654752f));
    if (j4 < 96) *reinterpret_cast<float4*>(cat + (size_t)t * Ed + j4 * 4) = rr;
    else         *reinterpret_cast<float4*>(v + (size_t)t * Dd + (j4 - 96) * 4) = rr;
}

// ---------------- V transpose: per batch [Sq x Dd] -> [Dd x Sq] ------------
__global__ void transpose_v(const float* __restrict__ v, float* __restrict__ vt) {
    __shared__ float tile[32][33];
    int b = blockIdx.z;
    int s0 = blockIdx.x * 32, d0 = blockIdx.y * 32;
    int x = threadIdx.x, y = threadIdx.y;
    const float* src = v + (size_t)b * Sq * Dd;
    float* dst = vt + (size_t)b * Dd * Sq;
#pragma unroll
    for (int i = 0; i < 32; i += 8)
        tile[y + i][x] = src[(size_t)(s0 + y + i) * Dd + d0 + x];
    __syncthreads();
#pragma unroll
    for (int i = 0; i < 32; i += 8)
        dst[(size_t)(d0 + y + i) * Sq + s0 + x] = tile[x][y + i];
}

// ---------------- causal row softmax ----------------
__global__ void softmax_kernel(float* __restrict__ p) {
    int i = blockIdx.x;
    int b = blockIdx.y;
    float* row = p + ((size_t)b * Sq + i) * Sq;
    int L = i + 1;
    int zend = ((i >> 7) + 1) << 7;
    int tid = threadIdx.x;
    const float scale = 0.14433756729740643f;
    __shared__ float sh[8];

    float m = -3.0e38f;
    for (int j = tid; j < L; j += 256) m = fmaxf(m, row[j]);
    m = warp_max(m);
    if ((tid & 31) == 0) sh[tid >> 5] = m;
    __syncthreads();
    float mm = sh[0];
#pragma unroll
    for (int k = 1; k < 8; k++) mm = fmaxf(mm, sh[k]);
    __syncthreads();

    float sum = 0.0f;
    for (int j = tid; j < L; j += 256) {
        float e = __expf((row[j] - mm) * scale);
        row[j] = e;
        sum += e;
    }
    sum = warp_sum(sum);
    if ((tid & 31) == 0) sh[tid >> 5] = sum;
    __syncthreads();
    float tot = sh[0];
#pragma unroll
    for (int k = 1; k < 8; k++) tot += sh[k];
    float inv = 1.0f / tot;

    for (int j = tid; j < L; j += 256) row[j] *= inv;
    for (int j = L + tid; j < zend; j += 256) row[j] = 0.0f;
}

// ---------------- SIMT SGEMM (logits only): C = A(MxK) * B(NxK)^T ----------
__global__ void __launch_bounds__(256, 2)
gemm_simt(const float* __restrict__ A, int lda,
          const float* __restrict__ B, int ldb,
          float* __restrict__ C, int ldc, int N, int K) {
    int bm = blockIdx.y * 128;
    int bn = blockIdx.x * 128;

    __shared__ float As[8][128];
    __shared__ float Bs[8][128];
    int tid = threadIdx.x;
    int tx = tid & 15, ty = tid >> 4;
    float acc[8][8] = {};

    int lrow = tid >> 1;
    int lkk  = (tid & 1) * 4;
    const float* Ap = A + (size_t)(bm + lrow) * lda + lkk;
    bool bvalid = (bn + lrow) < N;
    const float* Bp = B + (size_t)(bn + lrow) * ldb + lkk;

    for (int k0 = 0; k0 < K; k0 += 8) {
        float4 av = *reinterpret_cast<const float4*>(Ap + k0);
        float4 bv = bvalid ? *reinterpret_cast<const float4*>(Bp + k0)
                           : make_float4(0.f, 0.f, 0.f, 0.f);
        As[lkk+0][lrow]=av.x; As[lkk+1][lrow]=av.y; As[lkk+2][lrow]=av.z; As[lkk+3][lrow]=av.w;
        Bs[lkk+0][lrow]=bv.x; Bs[lkk+1][lrow]=bv.y; Bs[lkk+2][lrow]=bv.z; Bs[lkk+3][lrow]=bv.w;
        __syncthreads();
#pragma unroll
        for (int kk = 0; kk < 8; kk++) {
            float a[8], b[8];
            *reinterpret_cast<float4*>(&a[0]) = *reinterpret_cast<const float4*>(&As[kk][ty*8]);
            *reinterpret_cast<float4*>(&a[4]) = *reinterpret_cast<const float4*>(&As[kk][ty*8+4]);
            *reinterpret_cast<float4*>(&b[0]) = *reinterpret_cast<const float4*>(&Bs[kk][tx*8]);
            *reinterpret_cast<float4*>(&b[4]) = *reinterpret_cast<const float4*>(&Bs[kk][tx*8+4]);
#pragma unroll
            for (int i = 0; i < 8; i++)
#pragma unroll
                for (int j = 0; j < 8; j++)
                    acc[i][j] += a[i] * b[j];
        }
        __syncthreads();
    }
#pragma unroll
    for (int i = 0; i < 8; i++) {
        float* Crow = C + (size_t)(bm + ty * 8 + i) * ldc;
#pragma unroll
        for (int j = 0; j < 8; j++) {
            int n = bn + tx * 8 + j;
            if (n < N) Crow[n] = acc[i][j];
        }
    }
}

// ---------------- driver ----------------
extern "C" void kernel_launch(void* const* d_in, const int* in_sizes, int n_in,
                              void* d_out, int out_size) {
    const int*   q      = (const int*)  d_in[0];
    const float* freqs  = (const float*)d_in[1];
    const float* exp_w  = (const float*)d_in[2];   // (8, 1632, 384)
    const float* proj_w = (const float*)d_in[3];   // (8, 384, 768)
    const float* blk_g  = (const float*)d_in[4];
    const float* blk_b  = (const float*)d_in[5];
    const float* ln_g   = (const float*)d_in[6];
    const float* ln_b   = (const float*)d_in[7];
    const float* out_w  = (const float*)d_in[8];   // (100, 384)
    float* out = (float*)d_out;

    float *x, *xn, *h, *cat, *v, *vt, *p;
    cudaGetSymbolAddress((void**)&x,   g_x);
    cudaGetSymbolAddress((void**)&xn,  g_xn);
    cudaGetSymbolAddress((void**)&h,   g_h);
    cudaGetSymbolAddress((void**)&cat, g_cat);
    cudaGetSymbolAddress((void**)&v,   g_v);
    cudaGetSymbolAddress((void**)&vt,  g_vt);
    cudaGetSymbolAddress((void**)&p,   g_p);

    embed_ln_kernel<<<Tq, 128>>>(q, freqs, ln_g, ln_b, x);

    for (int blk = 0; blk < NBq; blk++) {
        ln_kernel<<<Tq, 128>>>(x, xn, blk_g + blk * Dd, blk_b + blk * Dd);

        // h = xn @ exp_w[blk]^T   (8192 x 1632, K=384)
        gemm_mma_launch(xn, Dd, 0,
                        exp_w + (size_t)blk * Hd * Dd, Dd, 0,
                        h, Hd, 0,
                        Tq, Hd, Dd, 1, false, 0);

        geglu_kernel<<<Tq, 192>>>(h, cat, v);

        // scores: qh @ kh^T per batch, causal tile-skip
        gemm_mma_launch(h,       Hd, (long long)Sq * Hd,
                        h + QKd, Hd, (long long)Sq * Hd,
                        p, Sq, (long long)Sq * Sq,
                        Sq, Sq, QKd, Bq, false, 1);

        softmax_kernel<<<dim3(Sq, Bq), 256>>>(p);

        transpose_v<<<dim3(Sq / 32, Dd / 32, Bq), dim3(32, 8)>>>(v, vt);

        // attn = P @ V  (B = V^T, N x K K-major), K capped causally
        gemm_mma_launch(p,  Sq, (long long)Sq * Sq,
                        vt, Sq, (long long)Dd * Sq,
                        cat + Dd, Ed, (long long)Sq * Ed,
                        Sq, Dd, Sq, Bq, false, 2);

        // x += cat @ proj_w[blk]^T
        gemm_mma_launch(cat, Ed, 0,
                        proj_w + (size_t)blk * Dd * Ed, Ed, 0,
                        x, Dd, 0,
                        Tq, Dd, Ed, 1, true, 0);
    }

    ln_kernel<<<Tq, 128>>>(x, xn, ln_g, ln_b);
    gemm_simt<<<dim3(1, Tq / 128), 256>>>(xn, Dd, out_w, Dd, out, VOCABq, VOCABq, Dd);
}

// round 9
// speedup vs baseline: 3.4999x; 1.5741x over previous
#include <cuda_runtime.h>
#include <cuda_bf16.h>
#include <cstdint>

// ---------------- problem constants ----------------
#define Bq      4
#define Sq      2048
#define Tq      (Bq * Sq)      // 8192 tokens
#define Dd      384
#define QKd     48
#define Ed      768
#define Hd      1632           // 2*QK + 2*E
#define NBq     8
#define VOCABq  100

// ---------------- scratch (static device globals; no cudaMalloc) -----------
__device__ float g_x[Tq * Dd];                        // residual stream
__device__ float g_xn[Tq * Dd];                       // final-LN output (fp32)
__device__ float g_h[(size_t)Tq * Hd];                // expand GEMM out (fp32)
__device__ float g_v[Tq * Dd];                        // V fp32 (pre-transpose)
__device__ float g_p[(size_t)Bq * Sq * Sq];           // raw scores fp32

#define AL16 __align__(16)
__device__ AL16 __nv_bfloat16 g_xnh[Tq * Dd],  g_xnl[Tq * Dd];
__device__ AL16 __nv_bfloat16 g_cath[(size_t)Tq * Ed], g_catl[(size_t)Tq * Ed];
__device__ AL16 __nv_bfloat16 g_vth[(size_t)Bq * Dd * Sq], g_vtl[(size_t)Bq * Dd * Sq];
__device__ AL16 __nv_bfloat16 g_ph[(size_t)Bq * Sq * Sq],  g_pl[(size_t)Bq * Sq * Sq];
__device__ AL16 __nv_bfloat16 g_qh[Tq * 64], g_ql[Tq * 64];   // qh padded K=64
__device__ AL16 __nv_bfloat16 g_kh[Tq * 64], g_kl[Tq * 64];   // kh padded K=64
__device__ AL16 __nv_bfloat16 g_ewh[NBq * Hd * Dd], g_ewl[NBq * Hd * Dd];
__device__ AL16 __nv_bfloat16 g_pwh[NBq * Dd * Ed], g_pwl[NBq * Dd * Ed];

// ================= low-level helpers =================
__device__ __forceinline__ uint32_t s2u(const void* p) {
    uint32_t a;
    asm("{ .reg .u64 t; cvta.to.shared.u64 t, %1; cvt.u32.u64 %0, t; }" : "=r"(a) : "l"(p));
    return a;
}
__device__ __forceinline__ void cpa16(uint32_t dst, const void* src, uint32_t sz) {
    asm volatile("cp.async.cg.shared.global [%0], [%1], 16, %2;"
                 :: "r"(dst), "l"(src), "r"(sz) : "memory");
}
__device__ __forceinline__ void cpa_commit() {
    asm volatile("cp.async.commit_group;" ::: "memory");
}
template <int NN>
__device__ __forceinline__ void cpa_wait() {
    asm volatile("cp.async.wait_group %0;" :: "n"(NN) : "memory");
}
// XOR swizzle within a 128B row (unit u16 ^ (row&7)) — conflict-free ldmatrix
__device__ __forceinline__ uint32_t swz(uint32_t off) { return off ^ ((off >> 3) & 0x70); }

__device__ __forceinline__ void ldm_x4(uint32_t addr, uint32_t* r) {
    asm volatile("ldmatrix.sync.aligned.m8n8.x4.shared.b16 {%0,%1,%2,%3}, [%4];"
                 : "=r"(r[0]), "=r"(r[1]), "=r"(r[2]), "=r"(r[3]) : "r"(addr));
}
__device__ __forceinline__ void mma16816(float* c, const uint32_t* a, const uint32_t* b) {
    asm volatile("mma.sync.aligned.m16n8k16.row.col.f32.bf16.bf16.f32 "
                 "{%0,%1,%2,%3}, {%4,%5,%6,%7}, {%8,%9}, {%0,%1,%2,%3};"
                 : "+f"(c[0]), "+f"(c[1]), "+f"(c[2]), "+f"(c[3])
                 : "r"(a[0]), "r"(a[1]), "r"(a[2]), "r"(a[3]), "r"(b[0]), "r"(b[1]));
}
__device__ __forceinline__ void split1(float v, __nv_bfloat16& h, __nv_bfloat16& l) {
    h = __float2bfloat16_rn(v);
    l = __float2bfloat16_rn(v - __bfloat162float(h));
}

// ================= bf16 HMMA GEMM: C = A(MxK) * B(NxK)^T, 3-term split =====
// Inputs pre-split (hi/lo bf16, K-contiguous). 128x128 CTA tile, BK=64,
// 8 warps (2x4), cp.async 2-stage double buffer, reg accumulators.
// K is a multiple of 64 at every call site. causal: 0=none, 1=skip bn>bm,
// 2=cap K at bm+128.
// OUTM: 0 = fp32 store, 1 = fp32 add, 2 = bf16 hi/lo pair store.
#define BTILE   16384                   // 128 rows x 64 bf16 x 2B
#define SHM_BF  (2 * 4 * BTILE + 128)   // two 4-tile buffers + align slack

template <int OUTM>
__global__ void __launch_bounds__(256, 1)
gemm_bf(const __nv_bfloat16* __restrict__ Ah_, const __nv_bfloat16* __restrict__ Al_,
        int lda, long long sA,
        const __nv_bfloat16* __restrict__ Bh_, const __nv_bfloat16* __restrict__ Bl_,
        int ldb, long long sB,
        float* __restrict__ Cf,
        __nv_bfloat16* __restrict__ Ch, __nv_bfloat16* __restrict__ Cl,
        int ldc, long long sC, int N, int K, int causal) {
    int bm = blockIdx.y * 128;
    int bn = blockIdx.x * 128;
    if (causal == 1 && bn > bm) return;
    int Keff = (causal == 2) ? ((bm + 128 < K) ? bm + 128 : K) : K;
    int nch = Keff >> 6;

    const __nv_bfloat16* Ah = Ah_ + (long long)blockIdx.z * sA;
    const __nv_bfloat16* Al = Al_ + (long long)blockIdx.z * sA;
    const __nv_bfloat16* Bh = Bh_ + (long long)blockIdx.z * sB;
    const __nv_bfloat16* Bl = Bl_ + (long long)blockIdx.z * sB;

    extern __shared__ char dsm[];
    uint32_t base = (s2u(dsm) + 127u) & ~127u;

    int tid = threadIdx.x;
    int wid = tid >> 5, lane = tid & 31;
    int m0w = (wid >> 2) * 64;
    int n0w = (wid & 3) * 32;

    // loader lanes: 1024 16B-units per tile; thread covers rows lrow+{0,32,64,96}
    int lrow = tid >> 3;       // 0..31
    int lu   = tid & 7;        // 0..7

    float acc[4][4][4];
#pragma unroll
    for (int i = 0; i < 4; i++)
#pragma unroll
        for (int j = 0; j < 4; j++)
#pragma unroll
            for (int e = 0; e < 4; e++) acc[i][j][e] = 0.0f;

    uint32_t a_row  = (uint32_t)(lane & 15);
    uint32_t a_colb = (uint32_t)((lane >> 4) * 16);
    uint32_t b_row  = (uint32_t)(((lane >> 4) << 3) + (lane & 7));
    uint32_t b_colb = (uint32_t)(((lane >> 3) & 1) * 16);

    auto load_chunk = [&](int ch, int bsel) {
        int k0 = ch << 6;
        uint32_t tb = base + (uint32_t)bsel * (4 * BTILE);
#pragma unroll
        for (int i = 0; i < 4; i++) {
            int row = lrow + i * 32;
            uint32_t soff = swz((uint32_t)row * 128u + (uint32_t)lu * 16u);
            size_t aoff = (size_t)(bm + row) * lda + k0 + lu * 8;
            cpa16(tb + soff,             Ah + aoff, 16u);
            cpa16(tb + BTILE + soff,     Al + aoff, 16u);
            uint32_t bsz = ((bn + row) < N) ? 16u : 0u;
            size_t boff = (size_t)(bn + row) * ldb + k0 + lu * 8;
            cpa16(tb + 2 * BTILE + soff, Bh + boff, bsz);
            cpa16(tb + 3 * BTILE + soff, Bl + boff, bsz);
        }
    };

    auto compute = [&](int bsel) {
        uint32_t tb  = base + (uint32_t)bsel * (4 * BTILE);
        uint32_t tAh = tb, tAl = tb + BTILE, tBh = tb + 2 * BTILE, tBl = tb + 3 * BTILE;
#pragma unroll
        for (int ks = 0; ks < 4; ks++) {
            uint32_t kbyte = (uint32_t)ks * 32u;
            uint32_t afrag[4][4], bhfrag[2][4], blfrag[2][4];
#pragma unroll
            for (int mt = 0; mt < 4; mt++) {
                uint32_t rr = (uint32_t)(m0w + mt * 16) + a_row;
                ldm_x4(tAh + swz(rr * 128u + kbyte + a_colb), afrag[mt]);
            }
#pragma unroll
            for (int bt = 0; bt < 2; bt++) {
                uint32_t rr = (uint32_t)(n0w + bt * 16) + b_row;
                uint32_t off = swz(rr * 128u + kbyte + b_colb);
                ldm_x4(tBh + off, bhfrag[bt]);
                ldm_x4(tBl + off, blfrag[bt]);
            }
#pragma unroll
            for (int mt = 0; mt < 4; mt++)
#pragma unroll
                for (int nt = 0; nt < 4; nt++) {
                    mma16816(acc[mt][nt], afrag[mt], &bhfrag[nt >> 1][(nt & 1) * 2]);
                    mma16816(acc[mt][nt], afrag[mt], &blfrag[nt >> 1][(nt & 1) * 2]);
                }
#pragma unroll
            for (int mt = 0; mt < 4; mt++) {
                uint32_t rr = (uint32_t)(m0w + mt * 16) + a_row;
                ldm_x4(tAl + swz(rr * 128u + kbyte + a_colb), afrag[mt]);
            }
#pragma unroll
            for (int mt = 0; mt < 4; mt++)
#pragma unroll
                for (int nt = 0; nt < 4; nt++)
                    mma16816(acc[mt][nt], afrag[mt], &bhfrag[nt >> 1][(nt & 1) * 2]);
        }
    };

    load_chunk(0, 0);
    cpa_commit();
    for (int ch = 0; ch < nch; ch++) {
        if (ch + 1 < nch) {
            load_chunk(ch + 1, (ch + 1) & 1);
            cpa_commit();
            cpa_wait<1>();
        } else {
            cpa_wait<0>();
        }
        __syncthreads();
        compute(ch & 1);
        __syncthreads();
    }

    // ---------------- epilogue ----------------
    float* CfB = (OUTM != 2) ? Cf + (long long)blockIdx.z * sC : nullptr;
    __nv_bfloat16* ChB = (OUTM == 2) ? Ch + (long long)blockIdx.z * sC : nullptr;
    __nv_bfloat16* ClB = (OUTM == 2) ? Cl + (long long)blockIdx.z * sC : nullptr;
#pragma unroll
    for (int mt = 0; mt < 4; mt++) {
        int row0 = bm + m0w + mt * 16 + (lane >> 2);
#pragma unroll
        for (int nt = 0; nt < 4; nt++) {
            int col = bn + n0w + nt * 8 + (lane & 3) * 2;
            float* c = acc[mt][nt];
#pragma unroll
            for (int half = 0; half < 2; half++) {
                int row = row0 + half * 8;
                float v0 = c[half * 2], v1 = c[half * 2 + 1];
                if (OUTM == 2) {
                    if (col + 1 < N) {
                        __nv_bfloat16 h0, l0, h1, l1;
                        split1(v0, h0, l0); split1(v1, h1, l1);
                        __nv_bfloat162 hv; hv.x = h0; hv.y = h1;
                        __nv_bfloat162 lv; lv.x = l0; lv.y = l1;
                        *reinterpret_cast<__nv_bfloat162*>(ChB + (size_t)row * ldc + col) = hv;
                        *reinterpret_cast<__nv_bfloat162*>(ClB + (size_t)row * ldc + col) = lv;
                    }
                } else {
                    float* Crow = CfB + (size_t)row * ldc;
                    if (col + 1 < N) {
                        float2 cv;
                        if (OUTM == 1) {
                            cv = *reinterpret_cast<float2*>(Crow + col);
                            cv.x += v0; cv.y += v1;
                        } else cv = make_float2(v0, v1);
                        *reinterpret_cast<float2*>(Crow + col) = cv;
                    } else if (col < N) {
                        Crow[col] = (OUTM == 1) ? (Crow[col] + v0) : v0;
                    }
                }
            }
        }
    }
}

template <int OUTM>
static inline void gemm_bf_launch(const __nv_bfloat16* Ah, const __nv_bfloat16* Al,
                                  int lda, long long sA,
                                  const __nv_bfloat16* Bh, const __nv_bfloat16* Bl,
                                  int ldb, long long sB,
                                  float* Cf, __nv_bfloat16* Ch, __nv_bfloat16* Cl,
                                  int ldc, long long sC,
                                  int M, int N, int K, int batch, int causal) {
    dim3 grid((N + 127) / 128, M / 128, batch);
    cudaFuncSetAttribute(gemm_bf<OUTM>, cudaFuncAttributeMaxDynamicSharedMemorySize, SHM_BF);
    gemm_bf<OUTM><<<grid, 256, SHM_BF>>>(Ah, Al, lda, sA, Bh, Bl, ldb, sB,
                                         Cf, Ch, Cl, ldc, sC, N, K, causal);
}

// ---------------- reductions ----------------
__device__ __forceinline__ float warp_sum(float v) {
#pragma unroll
    for (int o = 16; o; o >>= 1) v += __shfl_xor_sync(0xffffffffu, v, o);
    return v;
}
__device__ __forceinline__ float warp_max(float v) {
#pragma unroll
    for (int o = 16; o; o >>= 1) v = fmaxf(v, __shfl_xor_sync(0xffffffffu, v, o));
    return v;
}

// ---------------- weight split: fp32 -> bf16 hi/lo ----------------
__global__ void split_w_kernel(const float4* __restrict__ src,
                               __nv_bfloat162* __restrict__ h2,
                               __nv_bfloat162* __restrict__ l2, int n4) {
    int i = blockIdx.x * 256 + threadIdx.x;
    if (i >= n4) return;
    float4 x = src[i];
    __nv_bfloat162 ha = __floats2bfloat162_rn(x.x, x.y);
    __nv_bfloat162 hb = __floats2bfloat162_rn(x.z, x.w);
    __nv_bfloat162 la = __floats2bfloat162_rn(x.x - __bfloat162float(ha.x),
                                              x.y - __bfloat162float(ha.y));
    __nv_bfloat162 lb = __floats2bfloat162_rn(x.z - __bfloat162float(hb.x),
                                              x.w - __bfloat162float(hb.y));
    h2[2 * i] = ha; h2[2 * i + 1] = hb;
    l2[2 * i] = la; l2[2 * i + 1] = lb;
}

// ---------------- embed (sin/cos) + LayerNorm (fp32 out) ----------------
__global__ void embed_ln_kernel(const int* __restrict__ q,
                                const float* __restrict__ freqs,
                                const float* __restrict__ g,
                                const float* __restrict__ b,
                                float* __restrict__ y) {
    int t = blockIdx.x;
    int tid = threadIdx.x;
    float qv = (float)q[t];
    float v[3];
#pragma unroll
    for (int k = 0; k < 3; k++) {
        int d = tid + k * 128;
        if (d < Dd / 2) v[k] = sinf(qv * freqs[d]);
        else            v[k] = cosf(qv * freqs[d - Dd / 2]);
    }
    float s = v[0] + v[1] + v[2];
    float sq = v[0]*v[0] + v[1]*v[1] + v[2]*v[2];
    s = warp_sum(s); sq = warp_sum(sq);
    __shared__ float shs[4], shq[4], mr[2];
    if ((tid & 31) == 0) { shs[tid >> 5] = s; shq[tid >> 5] = sq; }
    __syncthreads();
    if (tid == 0) {
        float ts = shs[0]+shs[1]+shs[2]+shs[3], tq = shq[0]+shq[1]+shq[2]+shq[3];
        float mean = ts * (1.0f / Dd);
        float var  = tq * (1.0f / Dd) - mean * mean;
        mr[0] = mean; mr[1] = rsqrtf(var + 1e-5f);
    }
    __syncthreads();
    float mean = mr[0], rstd = mr[1];
    float* yr = y + (size_t)t * Dd;
#pragma unroll
    for (int k = 0; k < 3; k++) {
        int d = tid + k * 128;
        yr[d] = (v[k] - mean) * rstd * g[d] + b[d];
    }
}

// ---------------- LayerNorm, fp32 out (final LN) ----------------
__global__ void ln_kernel(const float* __restrict__ x, float* __restrict__ y,
                          const float* __restrict__ g, const float* __restrict__ b) {
    int t = blockIdx.x;
    int tid = threadIdx.x;
    const float* xr = x + (size_t)t * Dd;
    float v0 = xr[tid], v1 = xr[tid + 128], v2 = xr[tid + 256];
    float s  = v0 + v1 + v2;
    float sq = v0*v0 + v1*v1 + v2*v2;
    s = warp_sum(s); sq = warp_sum(sq);
    __shared__ float shs[4], shq[4], mr[2];
    if ((tid & 31) == 0) { shs[tid >> 5] = s; shq[tid >> 5] = sq; }
    __syncthreads();
    if (tid == 0) {
        float ts = shs[0]+shs[1]+shs[2]+shs[3], tq = shq[0]+shq[1]+shq[2]+shq[3];
        float mean = ts * (1.0f / Dd);
        float var  = tq * (1.0f / Dd) - mean * mean;
        mr[0] = mean; mr[1] = rsqrtf(var + 1e-5f);
    }
    __syncthreads();
    float mean = mr[0], rstd = mr[1];
    float* yr = y + (size_t)t * Dd;
    yr[tid]       = (v0 - mean) * rstd * g[tid]       + b[tid];
    yr[tid + 128] = (v1 - mean) * rstd * g[tid + 128] + b[tid + 128];
    yr[tid + 256] = (v2 - mean) * rstd * g[tid + 256] + b[tid + 256];
}

// ---------------- LayerNorm, bf16 hi/lo out (per-block LN) ----------------
__global__ void ln_bf16_kernel(const float* __restrict__ x,
                               __nv_bfloat16* __restrict__ yh,
                               __nv_bfloat16* __restrict__ yl,
                               const float* __restrict__ g,
                               const float* __restrict__ b) {
    int t = blockIdx.x;
    int tid = threadIdx.x;
    const float* xr = x + (size_t)t * Dd;
    float v0 = xr[tid], v1 = xr[tid + 128], v2 = xr[tid + 256];
    float s  = v0 + v1 + v2;
    float sq = v0*v0 + v1*v1 + v2*v2;
    s = warp_sum(s); sq = warp_sum(sq);
    __shared__ float shs[4], shq[4], mr[2];
    if ((tid & 31) == 0) { shs[tid >> 5] = s; shq[tid >> 5] = sq; }
    __syncthreads();
    if (tid == 0) {
        float ts = shs[0]+shs[1]+shs[2]+shs[3], tq = shq[0]+shq[1]+shq[2]+shq[3];
        float mean = ts * (1.0f / Dd);
        float var  = tq * (1.0f / Dd) - mean * mean;
        mr[0] = mean; mr[1] = rsqrtf(var + 1e-5f);
    }
    __syncthreads();
    float mean = mr[0], rstd = mr[1];
    size_t rb = (size_t)t * Dd;
#pragma unroll
    for (int k = 0; k < 3; k++) {
        int d = tid + k * 128;
        float vv = (k == 0 ? v0 : (k == 1 ? v1 : v2));
        float y = (vv - mean) * rstd * g[d] + b[d];
        __nv_bfloat16 hh, ll;
        split1(y, hh, ll);
        yh[rb + d] = hh; yl[rb + d] = ll;
    }
}

// ---------------- geglu: loc -> cat hi/lo, val -> V fp32 ----------------
__global__ void geglu_kernel(const float* __restrict__ h,
                             __nv_bfloat16* __restrict__ cath,
                             __nv_bfloat16* __restrict__ catl,
                             float* __restrict__ v) {
    int t = blockIdx.x;
    int j4 = threadIdx.x;   // 0..191, 4 cols each
    const float* hr = h + (size_t)t * Hd;
    float4 lin = *reinterpret_cast<const float4*>(hr + 2 * QKd + j4 * 4);
    float4 pg  = *reinterpret_cast<const float4*>(hr + 2 * QKd + Ed + j4 * 4);
    float4 r;
    r.x = lin.x * 0.5f * pg.x * (1.0f + erff(pg.x * 0.70710678118654752f));
    r.y = lin.y * 0.5f * pg.y * (1.0f + erff(pg.y * 0.70710678118654752f));
    r.z = lin.z * 0.5f * pg.z * (1.0f + erff(pg.z * 0.70710678118654752f));
    r.w = lin.w * 0.5f * pg.w * (1.0f + erff(pg.w * 0.70710678118654752f));
    if (j4 < 96) {
        __nv_bfloat162 ha = __floats2bfloat162_rn(r.x, r.y);
        __nv_bfloat162 hb = __floats2bfloat162_rn(r.z, r.w);
        __nv_bfloat162 la = __floats2bfloat162_rn(r.x - __bfloat162float(ha.x),
                                                  r.y - __bfloat162float(ha.y));
        __nv_bfloat162 lb = __floats2bfloat162_rn(r.z - __bfloat162float(hb.x),
                                                  r.w - __bfloat162float(hb.y));
        __nv_bfloat162* ch = reinterpret_cast<__nv_bfloat162*>(cath + (size_t)t * Ed + j4 * 4);
        __nv_bfloat162* cl = reinterpret_cast<__nv_bfloat162*>(catl + (size_t)t * Ed + j4 * 4);
        ch[0] = ha; ch[1] = hb; cl[0] = la; cl[1] = lb;
    } else {
        *reinterpret_cast<float4*>(v + (size_t)t * Dd + (j4 - 96) * 4) = r;
    }
}

// ---------------- qh/kh split, padded to K=64 ----------------
__global__ void qk_split_kernel(const float* __restrict__ h,
                                __nv_bfloat16* __restrict__ qh, __nv_bfloat16* __restrict__ ql,
                                __nv_bfloat16* __restrict__ kh, __nv_bfloat16* __restrict__ kl) {
    int t = blockIdx.x;
    int tid = threadIdx.x;          // 128
    int which = tid >> 6;           // 0: q, 1: k
    int d = tid & 63;
    float val = (d < QKd) ? h[(size_t)t * Hd + which * QKd + d] : 0.0f;
    __nv_bfloat16 hh, ll;
    split1(val, hh, ll);
    size_t idx = (size_t)t * 64 + d;
    if (which == 0) { qh[idx] = hh; ql[idx] = ll; }
    else            { kh[idx] = hh; kl[idx] = ll; }
}

// ---------------- V transpose: fp32 [Sq x Dd] -> bf16 hi/lo [Dd x Sq] ------
__global__ void transpose_v(const float* __restrict__ v,
                            __nv_bfloat16* __restrict__ vth,
                            __nv_bfloat16* __restrict__ vtl) {
    __shared__ float tile[32][33];
    int b = blockIdx.z;
    int s0 = blockIdx.x * 32, d0 = blockIdx.y * 32;
    int x = threadIdx.x, y = threadIdx.y;
    const float* src = v + (size_t)b * Sq * Dd;
    size_t dstb = (size_t)b * Dd * Sq;
#pragma unroll
    for (int i = 0; i < 32; i += 8)
        tile[y + i][x] = src[(size_t)(s0 + y + i) * Dd + d0 + x];
    __syncthreads();
#pragma unroll
    for (int i = 0; i < 32; i += 8) {
        float val = tile[x][y + i];
        __nv_bfloat16 hh, ll;
        split1(val, hh, ll);
        size_t idx = dstb + (size_t)(d0 + y + i) * Sq + s0 + x;
        vth[idx] = hh; vtl[idx] = ll;
    }
}

// ---------------- causal softmax: fp32 scores -> bf16 hi/lo probs ----------
__global__ void softmax_kernel(const float* __restrict__ p,
                               __nv_bfloat16* __restrict__ ph,
                               __nv_bfloat16* __restrict__ pl) {
    int i = blockIdx.x;
    int b = blockIdx.y;
    size_t off = ((size_t)b * Sq + i) * Sq;
    const float* row = p + off;
    int L = i + 1;
    int zend = ((i >> 7) + 1) << 7;
    int tid = threadIdx.x;   // 256
    const float scale = 0.14433756729740643f;
    __shared__ float sh[8];

    float m = -3.0e38f;
    float rv[8];
#pragma unroll
    for (int k = 0; k < 8; k++) {
        int j = tid + k * 256;
        rv[k] = (j < L) ? row[j] : -3.0e38f;
        m = fmaxf(m, rv[k]);
    }
    m = warp_max(m);
    if ((tid & 31) == 0) sh[tid >> 5] = m;
    __syncthreads();
    float mm = sh[0];
#pragma unroll
    for (int k = 1; k < 8; k++) mm = fmaxf(mm, sh[k]);
    __syncthreads();

    float sum = 0.0f;
#pragma unroll
    for (int k = 0; k < 8; k++) {
        int j = tid + k * 256;
        if (j < L) { rv[k] = __expf((rv[k] - mm) * scale); sum += rv[k]; }
    }
    sum = warp_sum(sum);
    if ((tid & 31) == 0) sh[tid >> 5] = sum;
    __syncthreads();
    float tot = sh[0];
#pragma unroll
    for (int k = 1; k < 8; k++) tot += sh[k];
    float inv = 1.0f / tot;

#pragma unroll
    for (int k = 0; k < 8; k++) {
        int j = tid + k * 256;
        if (j < zend) {
            float e = (j < L) ? rv[k] * inv : 0.0f;
            __nv_bfloat16 hh, ll;
            split1(e, hh, ll);
            ph[off + j] = hh; pl[off + j] = ll;
        }
    }
}

// ---------------- SIMT SGEMM (logits only): C = A(MxK) * B(NxK)^T ----------
__global__ void __launch_bounds__(256, 2)
gemm_simt(const float* __restrict__ A, int lda,
          const float* __restrict__ B, int ldb,
          float* __restrict__ C, int ldc, int N, int K) {
    int bm = blockIdx.y * 128;
    int bn = blockIdx.x * 128;

    __shared__ float As[8][128];
    __shared__ float Bs[8][128];
    int tid = threadIdx.x;
    int tx = tid & 15, ty = tid >> 4;
    float acc[8][8] = {};

    int lrow = tid >> 1;
    int lkk  = (tid & 1) * 4;
    const float* Ap = A + (size_t)(bm + lrow) * lda + lkk;
    bool bvalid = (bn + lrow) < N;
    const float* Bp = B + (size_t)(bn + lrow) * ldb + lkk;

    for (int k0 = 0; k0 < K; k0 += 8) {
        float4 av = *reinterpret_cast<const float4*>(Ap + k0);
        float4 bv = bvalid ? *reinterpret_cast<const float4*>(Bp + k0)
                           : make_float4(0.f, 0.f, 0.f, 0.f);
        As[lkk+0][lrow]=av.x; As[lkk+1][lrow]=av.y; As[lkk+2][lrow]=av.z; As[lkk+3][lrow]=av.w;
        Bs[lkk+0][lrow]=bv.x; Bs[lkk+1][lrow]=bv.y; Bs[lkk+2][lrow]=bv.z; Bs[lkk+3][lrow]=bv.w;
        __syncthreads();
#pragma unroll
        for (int kk = 0; kk < 8; kk++) {
            float a[8], b[8];
            *reinterpret_cast<float4*>(&a[0]) = *reinterpret_cast<const float4*>(&As[kk][ty*8]);
            *reinterpret_cast<float4*>(&a[4]) = *reinterpret_cast<const float4*>(&As[kk][ty*8+4]);
            *reinterpret_cast<float4*>(&b[0]) = *reinterpret_cast<const float4*>(&Bs[kk][tx*8]);
            *reinterpret_cast<float4*>(&b[4]) = *reinterpret_cast<const float4*>(&Bs[kk][tx*8+4]);
#pragma unroll
            for (int i = 0; i < 8; i++)
#pragma unroll
                for (int j = 0; j < 8; j++)
                    acc[i][j] += a[i] * b[j];
        }
        __syncthreads();
    }
#pragma unroll
    for (int i = 0; i < 8; i++) {
        float* Crow = C + (size_t)(bm + ty * 8 + i) * ldc;
#pragma unroll
        for (int j = 0; j < 8; j++) {
            int n = bn + tx * 8 + j;
            if (n < N) Crow[n] = acc[i][j];
        }
    }
}

// ---------------- driver ----------------
extern "C" void kernel_launch(void* const* d_in, const int* in_sizes, int n_in,
                              void* d_out, int out_size) {
    const int*   q      = (const int*)  d_in[0];
    const float* freqs  = (const float*)d_in[1];
    const float* exp_w  = (const float*)d_in[2];   // (8, 1632, 384)
    const float* proj_w = (const float*)d_in[3];   // (8, 384, 768)
    const float* blk_g  = (const float*)d_in[4];
    const float* blk_b  = (const float*)d_in[5];
    const float* ln_g   = (const float*)d_in[6];
    const float* ln_b   = (const float*)d_in[7];
    const float* out_w  = (const float*)d_in[8];   // (100, 384)
    float* out = (float*)d_out;

    float *x, *xn, *h, *v, *p;
    __nv_bfloat16 *xnh, *xnl, *cath, *catl, *vth, *vtl, *ph, *pl;
    __nv_bfloat16 *qh, *ql, *kh, *kl, *ewh, *ewl, *pwh, *pwl;
    cudaGetSymbolAddress((void**)&x,    g_x);
    cudaGetSymbolAddress((void**)&xn,   g_xn);
    cudaGetSymbolAddress((void**)&h,    g_h);
    cudaGetSymbolAddress((void**)&v,    g_v);
    cudaGetSymbolAddress((void**)&p,    g_p);
    cudaGetSymbolAddress((void**)&xnh,  g_xnh);  cudaGetSymbolAddress((void**)&xnl,  g_xnl);
    cudaGetSymbolAddress((void**)&cath, g_cath); cudaGetSymbolAddress((void**)&catl, g_catl);
    cudaGetSymbolAddress((void**)&vth,  g_vth);  cudaGetSymbolAddress((void**)&vtl,  g_vtl);
    cudaGetSymbolAddress((void**)&ph,   g_ph);   cudaGetSymbolAddress((void**)&pl,   g_pl);
    cudaGetSymbolAddress((void**)&qh,   g_qh);   cudaGetSymbolAddress((void**)&ql,   g_ql);
    cudaGetSymbolAddress((void**)&kh,   g_kh);   cudaGetSymbolAddress((void**)&kl,   g_kl);
    cudaGetSymbolAddress((void**)&ewh,  g_ewh);  cudaGetSymbolAddress((void**)&ewl,  g_ewl);
    cudaGetSymbolAddress((void**)&pwh,  g_pwh);  cudaGetSymbolAddress((void**)&pwl,  g_pwl);

    // pre-split weights (once per launch)
    {
        int n4e = NBq * Hd * Dd / 4;
        int n4p = NBq * Dd * Ed / 4;
        split_w_kernel<<<(n4e + 255) / 256, 256>>>(
            (const float4*)exp_w, (__nv_bfloat162*)ewh, (__nv_bfloat162*)ewl, n4e);
        split_w_kernel<<<(n4p + 255) / 256, 256>>>(
            (const float4*)proj_w, (__nv_bfloat162*)pwh, (__nv_bfloat162*)pwl, n4p);
    }

    embed_ln_kernel<<<Tq, 128>>>(q, freqs, ln_g, ln_b, x);

    for (int blk = 0; blk < NBq; blk++) {
        ln_bf16_kernel<<<Tq, 128>>>(x, xnh, xnl, blk_g + blk * Dd, blk_b + blk * Dd);

        // h = xn @ exp_w[blk]^T   (8192 x 1632, K=384) -> fp32
        gemm_bf_launch<0>(xnh, xnl, Dd, 0,
                          ewh + (size_t)blk * Hd * Dd, ewl + (size_t)blk * Hd * Dd, Dd, 0,
                          h, nullptr, nullptr, Hd, 0,
                          Tq, Hd, Dd, 1, 0);

        geglu_kernel<<<Tq, 192>>>(h, cath, catl, v);
        qk_split_kernel<<<Tq, 128>>>(h, qh, ql, kh, kl);

        // scores: qh @ kh^T per batch (K padded to 64), causal tile-skip
        gemm_bf_launch<0>(qh, ql, 64, (long long)Sq * 64,
                          kh, kl, 64, (long long)Sq * 64,
                          p, nullptr, nullptr, Sq, (long long)Sq * Sq,
                          Sq, Sq, 64, Bq, 1);

        softmax_kernel<<<dim3(Sq, Bq), 256>>>(p, ph, pl);

        transpose_v<<<dim3(Sq / 32, Dd / 32, Bq), dim3(32, 8)>>>(v, vth, vtl);

        // attn = P @ V -> cat[:, 384:768] as bf16 hi/lo; K capped causally
        gemm_bf_launch<2>(ph, pl, Sq, (long long)Sq * Sq,
                          vth, vtl, Sq, (long long)Dd * Sq,
                          nullptr, cath + Dd, catl + Dd, Ed, (long long)Sq * Ed,
                          Sq, Dd, Sq, Bq, 2);

        // x += cat @ proj_w[blk]^T
        gemm_bf_launch<1>(cath, catl, Ed, 0,
                          pwh + (size_t)blk * Dd * Ed, pwl + (size_t)blk * Dd * Ed, Ed, 0,
                          x, nullptr, nullptr, Dd, 0,
                          Tq, Dd, Ed, 1, 0);
    }

    ln_kernel<<<Tq, 128>>>(x, xn, ln_g, ln_b);
    gemm_simt<<<dim3(1, Tq / 128), 256>>>(xn, Dd, out_w, Dd, out, VOCABq, VOCABq, Dd);
}